// round 17
// baseline (speedup 1.0000x reference)
#include <cuda_runtime.h>
#include <cuda_fp16.h>
#include <math.h>

#define BATCH 16
#define CH    64
#define NPIX  25600          // 160*160
#define HID   256
#define KSEL  20480          // ceil(25600*0.8); divisible by 128
#define TOKB  128            // tokens per block
#define NTHR  128            // 4 warps x 32 tokens each
#define MAINBLK (KSEL / TOKB)   // 160
#define COPYTOK 512
#define COPYBLK (NPIX / COPYTOK) // 50
#define CAP   12288          // candidate cap for select compaction

#define ST_S  68             // sT fp32 row stride (272B)
#define WH_S  72             // half-chunk row stride, fp16 elems (144B)
#define HC_ELEMS 9216        // elems per half-chunk (W1half 64*72 + W2half 64*72)
#define HC_BYTES 18432
#define W2REG 9216           // byte offset of W2half within a half-chunk

// smem byte offsets (main kernel) -- TWO half-chunk buffers, occupancy 3
#define OFF_T    0            // 128*68*4  = 34816
#define OFF_W    34816        // 2 x 18432 = 36864
#define OFF_B1   71680        // 256 u32 (h2-packed bias1)
#define OFF_B2   72704        // 512
#define OFF_LS   73216        // 512
#define OFF_LB   73728        // 512
#define OFF_IDX  74240        // 512
#define SMEM_BYTES 74752      // x3 CTAs = 224256 <= 227KB

// ---------------- static scratch ----------------
__device__ unsigned char g_flags[BATCH * NPIX];
__device__ int           g_idx[BATCH * KSEL];
// pre-converted fp16 weights, half-chunk layout: hc = layer*4 + (j>>6)
__device__ __align__(16) unsigned short g_whc[8 * HC_ELEMS];

__device__ __forceinline__ unsigned fkey(float f) {
    unsigned u = __float_as_uint(f);
    return (u & 0x80000000u) ? ~u : (u | 0x80000000u);
}

__device__ __forceinline__ unsigned pack_h2(float2 v) {
    __half2 h = __float22half2_rn(v);
    return *(unsigned*)&h;
}

// gelu on a packed half2 (tanh approximation, all-fp16 math)
__device__ __forceinline__ unsigned gelu_h2(unsigned vu) {
    __half2 v = *(__half2*)&vu;
    const __half2 k0  = __floats2half2_rn(0.7978845608f, 0.7978845608f);
    const __half2 k01 = __floats2half2_rn(0.0356774081f, 0.0356774081f);  // k0*0.044715
    const __half2 hf  = __floats2half2_rn(0.5f, 0.5f);
    __half2 u = __hmul2(v, v);
    __half2 w = __hmul2(u, v);
    __half2 inner = __hfma2(w, k01, __hmul2(v, k0));
    unsigned tin = *(unsigned*)&inner, tout;
    asm("tanh.approx.f16x2 %0, %1;" : "=r"(tout) : "r"(tin));
    __half2 t = *(__half2*)&tout;
    __half2 hv = __hmul2(v, hf);
    __half2 res = __hfma2(hv, t, hv);
    return *(unsigned*)&res;
}

__device__ __forceinline__ void ldsm_x4t(unsigned* r, unsigned addr) {
    asm volatile("ldmatrix.sync.aligned.m8n8.x4.trans.shared.b16 {%0,%1,%2,%3}, [%4];"
                 : "=r"(r[0]), "=r"(r[1]), "=r"(r[2]), "=r"(r[3]) : "r"(addr));
}
__device__ __forceinline__ void mma_f16(float* d, const unsigned* a, unsigned b0, unsigned b1) {
    asm volatile("mma.sync.aligned.m16n8k16.row.col.f32.f16.f16.f32 "
                 "{%0,%1,%2,%3}, {%4,%5,%6,%7}, {%8,%9}, {%0,%1,%2,%3};"
                 : "+f"(d[0]), "+f"(d[1]), "+f"(d[2]), "+f"(d[3])
                 : "r"(a[0]), "r"(a[1]), "r"(a[2]), "r"(a[3]), "r"(b0), "r"(b1));
}
__device__ __forceinline__ void cp16(unsigned dst, const void* src) {
    asm volatile("cp.async.cg.shared.global [%0], [%1], 16;" :: "r"(dst), "l"(src));
}

// ---------------- kernel 1: fused prep + radix threshold + flags + compaction -------
__global__ void select_flags_kernel(const float* __restrict__ prop,
                                    const float* __restrict__ w1g, const float* __restrict__ w2g) {
    int tid = threadIdx.x;
    if (blockIdx.x >= BATCH) {
        // ---- prep: pre-convert weights to fp16 half-chunk layout ----
        int base = (blockIdx.x - BATCH) * 16384;
        #pragma unroll 4
        for (int q = 0; q < 16; ++q) {
            int idx = base + q * 1024 + tid;
            int layer = idx >> 14;
            int rem = idx & 16383;
            {   // w1: [layer][c][j] -> hc = layer*4 + (j>>6), elem c*WH_S + (j&63)
                int c = rem >> 8, j = rem & 255;
                __half h = __float2half_rn(w1g[idx]);
                g_whc[(layer * 4 + (j >> 6)) * HC_ELEMS + c * WH_S + (j & 63)] = *(unsigned short*)&h;
            }
            {   // w2: [layer][j][c] -> hc = layer*4 + (j>>6), elem 4608 + (j&63)*WH_S + c
                int j = rem >> 6, c = rem & 63;
                __half h = __float2half_rn(w2g[idx]);
                g_whc[(layer * 4 + (j >> 6)) * HC_ELEMS + 4608 + (j & 63) * WH_S + c] = *(unsigned short*)&h;
            }
        }
        return;
    }
    int b = blockIdx.x;
    const float* p = prop + (size_t)b * NPIX;
    extern __shared__ unsigned dyn[];
    unsigned* skey = dyn;                  // NPIX
    unsigned* hist = dyn + NPIX;           // 256
    unsigned* cand = dyn + NPIX + 256;     // CAP
    __shared__ unsigned s_prefix;
    __shared__ int s_k;
    __shared__ int s_n;
    __shared__ int s_cnt;
    __shared__ int s_neq;
    __shared__ int s_eq[1024];
    __shared__ unsigned wtot[8];
    int lane = tid & 31, w8 = tid >> 5;
    if (tid == 0) { s_prefix = 0u; s_k = KSEL; s_n = 0; s_cnt = 0; s_neq = 0; }
    if (tid < 256) hist[tid] = 0u;
    __syncthreads();
    // ---- load keys + top-byte histogram in one sweep ----
    for (int i = tid; i < NPIX; i += 1024) {
        unsigned u = fkey(p[i]);
        skey[i] = u;
        atomicAdd(&hist[u >> 24], 1u);
    }
    __syncthreads();
    // ---- digit select for shift=24 ----
    {
        int k = s_k;
        unsigned v = 0, h0 = 0;
        if (tid < 256) {
            v = hist[tid]; h0 = v;
            #pragma unroll
            for (int off = 1; off < 32; off <<= 1) {
                unsigned t = __shfl_down_sync(0xffffffffu, v, off);
                if (lane + off < 32) v += t;
            }
            if (lane == 0) wtot[w8] = v;
        }
        __syncthreads();
        if (tid < 256) {
            unsigned suf = v;
            for (int q = w8 + 1; q < 8; ++q) suf += wtot[q];
            if ((int)suf >= k && (int)(suf - h0) < k) {
                s_prefix = (unsigned)tid << 24;
                s_k = k - (int)(suf - h0);
            }
        }
        __syncthreads();
    }
    // ---- compact candidates matching top byte ----
    {
        unsigned pref8 = s_prefix;
        for (int i = tid; i < NPIX; i += 1024) {
            unsigned u = skey[i];
            if ((u & 0xFF000000u) == pref8) {
                int pos = atomicAdd(&s_n, 1);
                if (pos < CAP) cand[pos] = u;
            }
        }
    }
    __syncthreads();
    int ncand = s_n;
    bool ok = (ncand <= CAP);
    if (!ok) ncand = NPIX;          // fallback: scan full skey

    for (int pass = 2; pass >= 0; --pass) {
        int shift = pass * 8;
        if (tid < 256) hist[tid] = 0u;
        __syncthreads();
        unsigned prefix = s_prefix;
        unsigned highmask = 0xFFFFFFFFu << (shift + 8);
        const unsigned* src = ok ? cand : skey;
        for (int i = tid; i < ncand; i += 1024) {
            unsigned u = src[i];
            if ((u & highmask) == prefix)
                atomicAdd(&hist[(u >> shift) & 255u], 1u);
        }
        __syncthreads();
        int k = s_k;
        unsigned v = 0, h0 = 0;
        if (tid < 256) {
            v = hist[tid]; h0 = v;
            #pragma unroll
            for (int off = 1; off < 32; off <<= 1) {
                unsigned t = __shfl_down_sync(0xffffffffu, v, off);
                if (lane + off < 32) v += t;
            }
            if (lane == 0) wtot[w8] = v;
        }
        __syncthreads();
        if (tid < 256) {
            unsigned suf = v;
            for (int q = w8 + 1; q < 8; ++q) suf += wtot[q];
            if ((int)suf >= k && (int)(suf - h0) < k) {
                s_prefix = prefix | ((unsigned)tid << shift);
                s_k = k - (int)(suf - h0);
            }
        }
        __syncthreads();
    }

    // ---- flags + index compaction directly from smem keys (unordered g_idx) ----
    unsigned T = s_prefix;
    int ties = s_k;
    for (int i = tid; i < NPIX; i += 1024) {
        unsigned u = skey[i];
        int gt = (u > T), eq = (u == T);
        g_flags[(size_t)b * NPIX + i] = (unsigned char)gt;
        unsigned ball = __ballot_sync(0xffffffffu, gt);
        int pre = __popc(ball & ((1u << lane) - 1u));
        int basew = 0;
        if (lane == 0 && ball) basew = atomicAdd(&s_cnt, __popc(ball));
        basew = __shfl_sync(0xffffffffu, basew, 0);
        if (gt) g_idx[(size_t)b * KSEL + basew + pre] = i;
        unsigned balle = __ballot_sync(0xffffffffu, eq);
        if (balle) {
            int leader = __ffs(balle) - 1;
            int pree = __popc(balle & ((1u << lane) - 1u));
            int basee = 0;
            if (lane == leader) basee = atomicAdd(&s_neq, __popc(balle));
            basee = __shfl_sync(0xffffffffu, basee, leader);
            if (eq && basee + pree < 1024) s_eq[basee + pree] = i;
        }
    }
    __syncthreads();
    // ---- tie fixup: select the 'ties' lowest-index eq elements ----
    int n = s_neq;
    for (int e = tid; e < n; e += 1024) {
        int idx = s_eq[e];
        int rank = 0;
        for (int q = 0; q < n; ++q)
            rank += (s_eq[q] < idx) ? 1 : 0;
        if (rank < ties) {
            g_flags[(size_t)b * NPIX + idx] = 1;
            int pos = atomicAdd(&s_cnt, 1);
            g_idx[(size_t)b * KSEL + pos] = idx;
        }
    }
}

// ---------------- kernel 2: fused LN + MLP, half-chunk double-buffered weights ----------
__global__ void __launch_bounds__(NTHR, 3)
main_kernel(const float* __restrict__ x,
            const float* __restrict__ lnscale, const float* __restrict__ lnbias,
            const float* __restrict__ b1g, const float* __restrict__ b2g,
            float* __restrict__ out) {
    int tid = threadIdx.x;
    int b = blockIdx.y;

    // ---- merged pass-through copy path ----
    if (blockIdx.x >= MAINBLK) {
        int t0 = (blockIdx.x - MAINBLK) * COPYTOK + tid;
        const float* xb = x + (size_t)b * CH * NPIX;
        float* ob = out + (size_t)b * CH * NPIX;
        #pragma unroll
        for (int k = 0; k < COPYTOK / NTHR; ++k) {
            int i = t0 + k * NTHR;
            if (g_flags[(size_t)b * NPIX + i]) continue;
            #pragma unroll 8
            for (int c = 0; c < CH; ++c)
                ob[(size_t)c * NPIX + i] = xb[(size_t)c * NPIX + i];
        }
        return;
    }

    extern __shared__ char sm[];
    float* sT  = (float*)(sm + OFF_T);
    unsigned* sB1h = (unsigned*)(sm + OFF_B1);
    float* sB2 = (float*)(sm + OFF_B2);
    float* sLS = (float*)(sm + OFF_LS);
    float* sLB = (float*)(sm + OFF_LB);
    int*   sIdx = (int*)(sm + OFF_IDX);
    unsigned smem_base = (unsigned)__cvta_generic_to_shared(sm);

    int lane = tid & 31, w = tid >> 5;
    int tb = w * 32;
    int n0 = blockIdx.x * TOKB;

    int r = lane >> 2;
    int c2 = (lane & 3) * 2;
    int r15 = lane & 15;
    int colsel = ((lane >> 4) & 1) * 8;
    int row0a = tb + r,      row1a = row0a + 8;
    int row0b = tb + 16 + r, row1b = row0b + 8;

    // ---- stage half-chunk 0 (async, overlaps gathers) ----
    {
        const char* src = (const char*)g_whc;
        unsigned dst = smem_base + OFF_W;
        for (int i = tid * 16; i < HC_BYTES; i += NTHR * 16) cp16(dst + i, src + i);
        asm volatile("cp.async.commit_group;");
    }

    // ---- token index list + params, then gather x tile ----
    sIdx[tid] = g_idx[(size_t)b * KSEL + n0 + tid];
    for (int i = tid; i < HID; i += NTHR)
        sB1h[i] = pack_h2(make_float2(b1g[2 * i], b1g[2 * i + 1]));
    if (tid < 2 * CH) {
        sB2[tid] = b2g[tid];
        sLS[tid] = lnscale[tid];
        sLB[tid] = lnbias[tid];
    }
    __syncthreads();
    const float* xb = x + (size_t)b * CH * NPIX;
    {
        int gi = sIdx[tid];
        #pragma unroll 8
        for (int c = 0; c < CH; ++c)
            sT[tid * ST_S + c] = xb[(size_t)c * NPIX + gi];
    }
    __syncthreads();

    for (int layer = 0; layer < 2; ++layer) {
        // ---- LN stats: 1 lane per token ----
        float mu, rs;
        {
            const float* rowp = sT + (tb + lane) * ST_S;
            float s = 0.f, s2 = 0.f;
            #pragma unroll
            for (int k = 0; k < 64; k += 4) {
                float4 v = *(const float4*)(rowp + k);
                s  += v.x + v.y + v.z + v.w;
                s2 += v.x * v.x + v.y * v.y + v.z * v.z + v.w * v.w;
            }
            mu = s * (1.f / 64.f);
            float var = s2 * (1.f / 64.f) - mu * mu;
            rs = rsqrtf(var + 1e-5f);
        }
        float mu0a = __shfl_sync(0xffffffffu, mu, r);
        float rs0a = __shfl_sync(0xffffffffu, rs, r);
        float mu1a = __shfl_sync(0xffffffffu, mu, r + 8);
        float rs1a = __shfl_sync(0xffffffffu, rs, r + 8);
        float mu0b = __shfl_sync(0xffffffffu, mu, r + 16);
        float rs0b = __shfl_sync(0xffffffffu, rs, r + 16);
        float mu1b = __shfl_sync(0xffffffffu, mu, r + 24);
        float rs1b = __shfl_sync(0xffffffffu, rs, r + 24);

        // ---- build GEMM1 A-fragments (Xn), fp16, two M-tiles ----
        unsigned aXa[16], aXb[16];
        #pragma unroll
        for (int kt = 0; kt < 4; ++kt) {
            int cA = kt * 16 + c2;
            float2 lsA = *(const float2*)(sLS + layer * 64 + cA);
            float2 lbA = *(const float2*)(sLB + layer * 64 + cA);
            float2 lsB = *(const float2*)(sLS + layer * 64 + cA + 8);
            float2 lbB = *(const float2*)(sLB + layer * 64 + cA + 8);
            float2 v;
            v = *(const float2*)(sT + row0a * ST_S + cA);
            v.x = (v.x - mu0a) * rs0a * lsA.x + lbA.x;
            v.y = (v.y - mu0a) * rs0a * lsA.y + lbA.y;
            aXa[kt * 4 + 0] = pack_h2(v);
            v = *(const float2*)(sT + row1a * ST_S + cA);
            v.x = (v.x - mu1a) * rs1a * lsA.x + lbA.x;
            v.y = (v.y - mu1a) * rs1a * lsA.y + lbA.y;
            aXa[kt * 4 + 1] = pack_h2(v);
            v = *(const float2*)(sT + row0a * ST_S + cA + 8);
            v.x = (v.x - mu0a) * rs0a * lsB.x + lbB.x;
            v.y = (v.y - mu0a) * rs0a * lsB.y + lbB.y;
            aXa[kt * 4 + 2] = pack_h2(v);
            v = *(const float2*)(sT + row1a * ST_S + cA + 8);
            v.x = (v.x - mu1a) * rs1a * lsB.x + lbB.x;
            v.y = (v.y - mu1a) * rs1a * lsB.y + lbB.y;
            aXa[kt * 4 + 3] = pack_h2(v);

            v = *(const float2*)(sT + row0b * ST_S + cA);
            v.x = (v.x - mu0b) * rs0b * lsA.x + lbA.x;
            v.y = (v.y - mu0b) * rs0b * lsA.y + lbA.y;
            aXb[kt * 4 + 0] = pack_h2(v);
            v = *(const float2*)(sT + row1b * ST_S + cA);
            v.x = (v.x - mu1b) * rs1b * lsA.x + lbA.x;
            v.y = (v.y - mu1b) * rs1b * lsA.y + lbA.y;
            aXb[kt * 4 + 1] = pack_h2(v);
            v = *(const float2*)(sT + row0b * ST_S + cA + 8);
            v.x = (v.x - mu0b) * rs0b * lsB.x + lbB.x;
            v.y = (v.y - mu0b) * rs0b * lsB.y + lbB.y;
            aXb[kt * 4 + 2] = pack_h2(v);
            v = *(const float2*)(sT + row1b * ST_S + cA + 8);
            v.x = (v.x - mu1b) * rs1b * lsB.x + lbB.x;
            v.y = (v.y - mu1b) * rs1b * lsB.y + lbB.y;
            aXb[kt * 4 + 3] = pack_h2(v);
        }

        float d2a[32], d2b[32];
        #pragma unroll
        for (int i = 0; i < 32; ++i) { d2a[i] = 0.f; d2b[i] = 0.f; }

        for (int q = 0; q < 4; ++q) {
            int hc = layer * 4 + q;
            unsigned wbase = smem_base + OFF_W + (hc & 1) * HC_BYTES;

            __syncthreads();   // all warps done reading buf[(hc+1)&1] (= hc-1's data)
            if (hc + 1 < 8) {
                const char* src = (const char*)(g_whc + (hc + 1) * HC_ELEMS);
                unsigned dst = smem_base + OFF_W + ((hc + 1) & 1) * HC_BYTES;
                for (int i = tid * 16; i < HC_BYTES; i += NTHR * 16) cp16(dst + i, src + i);
                asm volatile("cp.async.commit_group;");
                asm volatile("cp.async.wait_group 1;");
            } else {
                asm volatile("cp.async.wait_group 0;");
            }
            __syncthreads();   // half-chunk hc visible to all warps

            // ---- epilogue-lag pipeline over jg=0..3 ----
            unsigned a2a[4], a2b[4];
            #pragma unroll
            for (int jg = 0; jg < 4; ++jg) {
                float d1a[8], d1b[8];
                #pragma unroll
                for (int i = 0; i < 8; ++i) { d1a[i] = 0.f; d1b[i] = 0.f; }
                #pragma unroll
                for (int kt = 0; kt < 4; ++kt) {
                    unsigned bh[4];
                    unsigned boff = (unsigned)((kt * 16 + r15) * WH_S + jg * 16 + colsel) * 2;
                    ldsm_x4t(bh, wbase + boff);
                    mma_f16(d1a,     aXa + kt * 4, bh[0], bh[1]);
                    mma_f16(d1b,     aXb + kt * 4, bh[0], bh[1]);
                    mma_f16(d1a + 4, aXa + kt * 4, bh[2], bh[3]);
                    mma_f16(d1b + 4, aXb + kt * 4, bh[2], bh[3]);
                }
                if (jg > 0) {
                    int jp = jg - 1;
                    #pragma unroll
                    for (int np = 0; np < 4; ++np) {
                        unsigned bh[4];
                        unsigned boff = W2REG + (unsigned)((jp * 16 + r15) * WH_S + np * 16 + colsel) * 2;
                        ldsm_x4t(bh, wbase + boff);
                        mma_f16(d2a + np * 8,     a2a, bh[0], bh[1]);
                        mma_f16(d2b + np * 8,     a2b, bh[0], bh[1]);
                        mma_f16(d2a + np * 8 + 4, a2a, bh[2], bh[3]);
                        mma_f16(d2b + np * 8 + 4, a2b, bh[2], bh[3]);
                    }
                }
                {
                    int pb = (layer * HID + q * 64 + jg * 16) >> 1;
                    unsigned b0 = sB1h[pb + (c2 >> 1)];
                    unsigned b8 = sB1h[pb + 4 + (c2 >> 1)];
                    __half2 b0h = *(__half2*)&b0, b8h = *(__half2*)&b8;
                    __half2 t; unsigned tu;
                    #define GEPI(dst, dd, bb) \
                        tu = pack_h2(make_float2((dd)[0], (dd)[1])); \
                        t = __hadd2(*(__half2*)&tu, bb); \
                        dst = gelu_h2(*(unsigned*)&t);
                    GEPI(a2a[0], d1a + 0, b0h); GEPI(a2a[1], d1a + 2, b0h);
                    GEPI(a2a[2], d1a + 4, b8h); GEPI(a2a[3], d1a + 6, b8h);
                    GEPI(a2b[0], d1b + 0, b0h); GEPI(a2b[1], d1b + 2, b0h);
                    GEPI(a2b[2], d1b + 4, b8h); GEPI(a2b[3], d1b + 6, b8h);
                    #undef GEPI
                }
            }
            // drain: GEMM2 for jg=3 (buffer hc still valid)
            #pragma unroll
            for (int np = 0; np < 4; ++np) {
                unsigned bh[4];
                unsigned boff = W2REG + (unsigned)((3 * 16 + r15) * WH_S + np * 16 + colsel) * 2;
                ldsm_x4t(bh, wbase + boff);
                mma_f16(d2a + np * 8,     a2a, bh[0], bh[1]);
                mma_f16(d2b + np * 8,     a2b, bh[0], bh[1]);
                mma_f16(d2a + np * 8 + 4, a2a, bh[2], bh[3]);
                mma_f16(d2b + np * 8 + 4, a2b, bh[2], bh[3]);
            }
        }

        // ---- unconditional residual add into sT (warp-local rows) ----
        {
            #pragma unroll
            for (int nt = 0; nt < 8; ++nt) {
                int c0 = nt * 8 + c2;
                float2 bv = *(const float2*)(sB2 + layer * 64 + c0);
                sT[row0a * ST_S + c0]     += d2a[nt * 4 + 0] + bv.x;
                sT[row0a * ST_S + c0 + 1] += d2a[nt * 4 + 1] + bv.y;
                sT[row1a * ST_S + c0]     += d2a[nt * 4 + 2] + bv.x;
                sT[row1a * ST_S + c0 + 1] += d2a[nt * 4 + 3] + bv.y;
                sT[row0b * ST_S + c0]     += d2b[nt * 4 + 0] + bv.x;
                sT[row0b * ST_S + c0 + 1] += d2b[nt * 4 + 1] + bv.y;
                sT[row1b * ST_S + c0]     += d2b[nt * 4 + 2] + bv.x;
                sT[row1b * ST_S + c0 + 1] += d2b[nt * 4 + 3] + bv.y;
            }
        }
        __syncwarp();
    }

    // ---- scatter store ----
    __syncthreads();
    float* ob = out + (size_t)b * CH * NPIX;
    {
        int gi = sIdx[tid];
        #pragma unroll 8
        for (int c = 0; c < CH; ++c)
            ob[(size_t)c * NPIX + gi] = sT[tid * ST_S + c];
    }
}

// ---------------- launch ----------------
extern "C" void kernel_launch(void* const* d_in, const int* in_sizes, int n_in,
                              void* d_out, int out_size) {
    const float* x    = (const float*)d_in[0];
    const float* prop = (const float*)d_in[1];
    const float* lns  = (const float*)d_in[2];
    const float* lnb  = (const float*)d_in[3];
    const float* w1   = (const float*)d_in[4];
    const float* b1   = (const float*)d_in[5];
    const float* w2   = (const float*)d_in[6];
    const float* b2   = (const float*)d_in[7];
    float* out = (float*)d_out;

    cudaFuncSetAttribute(main_kernel, cudaFuncAttributeMaxDynamicSharedMemorySize, SMEM_BYTES);
    int sel_smem = (NPIX + 256 + CAP) * 4;
    cudaFuncSetAttribute(select_flags_kernel, cudaFuncAttributeMaxDynamicSharedMemorySize, sel_smem);

    select_flags_kernel<<<BATCH + 2, 1024, sel_smem>>>(prop, w1, w2);
    dim3 grid(MAINBLK + COPYBLK, BATCH);
    main_kernel<<<grid, NTHR, SMEM_BYTES>>>(x, lns, lnb, b1, b2, out);
}